// round 2
// baseline (speedup 1.0000x reference)
#include <cuda_runtime.h>

#define N_NODESC 100000
#define N_EDGESC 1600000
#define IN_CH    128
#define NH       64
#define OUT_CHC  40
#define ALPHA_F  0.1f

#define SCAN_CHUNK 1024
#define SCAN_NBLK  ((N_NODESC + SCAN_CHUNK - 1) / SCAN_CHUNK)   // 98

// ---------------- scratch (static device arrays; no runtime allocation) ----------------
__device__ int   g_is64;
__device__ int   g_deg[N_NODESC];
__device__ int   g_rowptr[N_NODESC + 1];
__device__ int   g_cursor[N_NODESC];
__device__ int   g_bsum[SCAN_NBLK];
__device__ int   g_boff[SCAN_NBLK];
__device__ int   g_row32[N_EDGESC];
__device__ int   g_col32[N_EDGESC];
__device__ int   g_src[N_EDGESC];
__device__ float g_enorm[N_EDGESC];
__device__ float g_dinv[N_NODESC];
__device__ float g_h0[N_NODESC * NH];
__device__ float g_hA[N_NODESC * NH];
__device__ float g_hB[N_NODESC * NH];

// ---------------- dtype detection ----------------
// JAX default config silently makes "int64" arrays int32. Detect which layout
// we actually got: for little-endian int64 data, every odd int32 word is the
// high half (node ids < 2^31 -> 0). For int32 data, odd words are random ids.
__global__ void k_detect(const int* __restrict__ ei) {
    int nz = 0;
    for (int i = 1; i < 512; i += 2) nz |= ei[i];
    g_is64 = (nz == 0) ? 1 : 0;
}

// ---------------- preprocessing ----------------
__global__ void k_zero_deg() {
    int i = blockIdx.x * blockDim.x + threadIdx.x;
    if (i < N_NODESC) g_deg[i] = 0;
}

// decode edge index -> int32 pair, histogram in-degree by col
__global__ void k_degree(const int* __restrict__ ei) {
    int e = blockIdx.x * blockDim.x + threadIdx.x;
    if (e >= N_EDGESC) return;
    int r, c;
    if (g_is64) {
        r = ei[2 * e];
        c = ei[2 * (N_EDGESC + e)];
    } else {
        r = ei[e];
        c = ei[N_EDGESC + e];
    }
    if ((unsigned)r >= N_NODESC) r = 0;
    if ((unsigned)c >= N_NODESC) c = 0;
    g_row32[e] = r;
    g_col32[e] = c;
    atomicAdd(&g_deg[c], 1);
}

__global__ void k_dinv() {
    int i = blockIdx.x * blockDim.x + threadIdx.x;
    if (i >= N_NODESC) return;
    int d = g_deg[i];
    g_dinv[i] = (d > 0) ? rsqrtf((float)d) : 0.0f;
}

__global__ void k_scan_bsum() {
    __shared__ int s[SCAN_CHUNK];
    int t = threadIdx.x;
    int i = blockIdx.x * SCAN_CHUNK + t;
    s[t] = (i < N_NODESC) ? g_deg[i] : 0;
    __syncthreads();
    for (int off = SCAN_CHUNK / 2; off > 0; off >>= 1) {
        if (t < off) s[t] += s[t + off];
        __syncthreads();
    }
    if (t == 0) g_bsum[blockIdx.x] = s[0];
}

__global__ void k_scan_top() {
    __shared__ int s[128];
    int t = threadIdx.x;
    s[t] = (t < SCAN_NBLK) ? g_bsum[t] : 0;
    __syncthreads();
    if (t == 0) {
        int acc = 0;
        for (int b = 0; b < SCAN_NBLK; b++) { int v = s[b]; s[b] = acc; acc += v; }
        g_rowptr[N_NODESC] = N_EDGESC;
    }
    __syncthreads();
    if (t < SCAN_NBLK) g_boff[t] = s[t];
}

__global__ void k_scan_within() {
    __shared__ int s[SCAN_CHUNK];
    int t = threadIdx.x;
    int i = blockIdx.x * SCAN_CHUNK + t;
    int v = (i < N_NODESC) ? g_deg[i] : 0;
    s[t] = v;
    __syncthreads();
    for (int off = 1; off < SCAN_CHUNK; off <<= 1) {
        int x = (t >= off) ? s[t - off] : 0;
        __syncthreads();
        s[t] += x;
        __syncthreads();
    }
    int excl = s[t] - v + g_boff[blockIdx.x];
    if (i < N_NODESC) { g_rowptr[i] = excl; g_cursor[i] = excl; }
}

__global__ void k_scatter() {
    int e = blockIdx.x * blockDim.x + threadIdx.x;
    if (e >= N_EDGESC) return;
    int r = g_row32[e];
    int c = g_col32[e];
    float nm = g_dinv[r] * g_dinv[c];
    int pos = atomicAdd(&g_cursor[c], 1);
    if ((unsigned)pos < N_EDGESC) {
        g_src[pos]   = r;
        g_enorm[pos] = nm;
    }
}

// ---------------- fc1: h = relu(x @ W1^T + b1), x[N,128], W1[64,128] ----------------
// block = 256 threads = 32 output-pairs x 8 node-pairs -> 16 nodes per group
#define FC1_NODES 16
__global__ __launch_bounds__(256, 4) void k_fc1(const float* __restrict__ x,
                                                const float* __restrict__ w,
                                                const float* __restrict__ b) {
    __shared__ float sW[IN_CH * NH];        // [k][j] transposed, 32 KB
    __shared__ float sX[FC1_NODES][IN_CH + 1];
    __shared__ float sB[NH];
    for (int i = threadIdx.x; i < IN_CH * NH; i += 256) {
        int j = i >> 7, k = i & 127;        // w is [j][k]
        sW[k * NH + j] = w[i];
    }
    if (threadIdx.x < NH) sB[threadIdx.x] = b[threadIdx.x];
    __syncthreads();

    int jp = threadIdx.x & 31;              // output pair index (2 outputs)
    int np = threadIdx.x >> 5;              // node-pair index 0..7
    int na = np * 2, nb = np * 2 + 1;
    const int ngroups = N_NODESC / FC1_NODES;   // 6250 exact

    for (int g = blockIdx.x; g < ngroups; g += gridDim.x) {
        int base = g * FC1_NODES;
        __syncthreads();
        for (int i = threadIdx.x; i < FC1_NODES * IN_CH; i += 256) {
            int n = i >> 7, k = i & 127;
            sX[n][k] = x[(long)(base + n) * IN_CH + k];
        }
        __syncthreads();

        float b0 = sB[2 * jp], b1 = sB[2 * jp + 1];
        float a00 = b0, a01 = b1, a10 = b0, a11 = b1;
        #pragma unroll 8
        for (int k = 0; k < IN_CH; k++) {
            float2 wv = *(const float2*)&sW[k * NH + 2 * jp];
            float xa = sX[na][k];
            float xb = sX[nb][k];
            a00 = fmaf(wv.x, xa, a00);
            a01 = fmaf(wv.y, xa, a01);
            a10 = fmaf(wv.x, xb, a10);
            a11 = fmaf(wv.y, xb, a11);
        }
        float2 oa = make_float2(fmaxf(a00, 0.f), fmaxf(a01, 0.f));
        float2 ob = make_float2(fmaxf(a10, 0.f), fmaxf(a11, 0.f));
        *(float2*)&g_h0[(long)(base + na) * NH + 2 * jp] = oa;
        *(float2*)&g_h0[(long)(base + nb) * NH + 2 * jp] = ob;
    }
}

// ---------------- fused GCN2 layer: agg + mix + 64x64 matmul + relu ----------------
// warp per node; block = 256 threads = 8 nodes
__global__ __launch_bounds__(256, 6) void k_layer(const float* __restrict__ hin,
                                                  const float* __restrict__ h0,
                                                  const float* __restrict__ W,
                                                  float* __restrict__ hout) {
    __shared__ float sW[NH * NH];           // 16 KB, W[k][j] row-major (matches conv_w[i])
    __shared__ float sMix[8][NH];
    for (int i = threadIdx.x; i < NH * NH; i += 256) sW[i] = W[i];
    __syncthreads();

    int warp = threadIdx.x >> 5;
    int lane = threadIdx.x & 31;
    int node = blockIdx.x * 8 + warp;
    if (node >= N_NODESC) return;

    int s = g_rowptr[node];
    int e = g_rowptr[node + 1];
    float ax = 0.f, ay = 0.f;
    #pragma unroll 4
    for (int i = s; i < e; i++) {
        int   src = __ldg(&g_src[i]);
        float nm  = __ldg(&g_enorm[i]);
        float2 v  = *(const float2*)(hin + (long)src * NH + lane * 2);
        ax = fmaf(nm, v.x, ax);
        ay = fmaf(nm, v.y, ay);
    }
    float2 h0v = *(const float2*)(h0 + (long)node * NH + lane * 2);
    float mx = fmaf(1.0f - ALPHA_F, ax, ALPHA_F * h0v.x);
    float my = fmaf(1.0f - ALPHA_F, ay, ALPHA_F * h0v.y);
    *(float2*)&sMix[warp][lane * 2] = make_float2(mx, my);
    __syncwarp();

    float o0 = 0.f, o1 = 0.f;
    #pragma unroll
    for (int k = 0; k < NH; k++) {
        float m = sMix[warp][k];
        float2 wv = *(const float2*)&sW[k * NH + lane * 2];
        o0 = fmaf(m, wv.x, o0);
        o1 = fmaf(m, wv.y, o1);
    }
    float2 out = make_float2(fmaxf(o0, 0.f), fmaxf(o1, 0.f));
    *(float2*)(hout + (long)node * NH + lane * 2) = out;
}

// ---------------- fc2: out = h @ W2^T + b2, h[N,64], W2[40,64] ----------------
// block = 320 threads = 8 nodes x 40 outputs
__global__ __launch_bounds__(320, 4) void k_fc2(const float* __restrict__ hin,
                                                const float* __restrict__ w,
                                                const float* __restrict__ b,
                                                float* __restrict__ out) {
    __shared__ float sW[NH * OUT_CHC];      // [k][j] transposed, 10 KB
    __shared__ float sH[8][NH + 1];
    __shared__ float sB[OUT_CHC];
    for (int i = threadIdx.x; i < NH * OUT_CHC; i += 320) {
        int j = i >> 6, k = i & 63;         // w is [j][k]
        sW[k * OUT_CHC + j] = w[i];
    }
    if (threadIdx.x < OUT_CHC) sB[threadIdx.x] = b[threadIdx.x];
    __syncthreads();

    int tn = threadIdx.x / OUT_CHC;         // node 0..7
    int j  = threadIdx.x % OUT_CHC;
    const int ngroups = N_NODESC / 8;       // 12500 exact

    for (int g = blockIdx.x; g < ngroups; g += gridDim.x) {
        int base = g * 8;
        __syncthreads();
        for (int i = threadIdx.x; i < 8 * NH; i += 320) {
            int n = i >> 6, k = i & 63;
            sH[n][k] = hin[(long)(base + n) * NH + k];
        }
        __syncthreads();
        float acc = sB[j];
        #pragma unroll 8
        for (int k = 0; k < NH; k++)
            acc = fmaf(sH[tn][k], sW[k * OUT_CHC + j], acc);
        out[(long)(base + tn) * OUT_CHC + j] = acc;
    }
}

// ---------------- launch ----------------
extern "C" void kernel_launch(void* const* d_in, const int* in_sizes, int n_in,
                              void* d_out, int out_size) {
    const float* x      = (const float*)d_in[0];
    const int*   ei     = (const int*)d_in[1];   // int32 OR packed int64 (auto-detected)
    // d_in[2] = batch_graph (unused)
    const float* fc1_w  = (const float*)d_in[3];
    const float* fc1_b  = (const float*)d_in[4];
    const float* conv_w = (const float*)d_in[5];
    const float* fc2_w  = (const float*)d_in[6];
    const float* fc2_b  = (const float*)d_in[7];
    float*       out    = (float*)d_out;

    const int nb_nodes = (N_NODESC + 255) / 256;
    const int nb_edges = (N_EDGESC + 255) / 256;

    // preprocessing: dtype detect -> degree -> dinv -> CSR
    k_detect<<<1, 1>>>(ei);
    k_zero_deg<<<nb_nodes, 256>>>();
    k_degree<<<nb_edges, 256>>>(ei);
    k_dinv<<<nb_nodes, 256>>>();
    k_scan_bsum<<<SCAN_NBLK, SCAN_CHUNK>>>();
    k_scan_top<<<1, 128>>>();
    k_scan_within<<<SCAN_NBLK, SCAN_CHUNK>>>();
    k_scatter<<<nb_edges, 256>>>();

    // fc1
    k_fc1<<<592, 256>>>(x, fc1_w, fc1_b);

    // resolve device pointers for ping-pong buffers
    float* h0; float* hA; float* hB;
    cudaGetSymbolAddress((void**)&h0, g_h0);
    cudaGetSymbolAddress((void**)&hA, g_hA);
    cudaGetSymbolAddress((void**)&hB, g_hB);

    const int nb_layer = (N_NODESC + 7) / 8;
    k_layer<<<nb_layer, 256>>>(h0, h0, conv_w + 0 * NH * NH, hA);
    k_layer<<<nb_layer, 256>>>(hA, h0, conv_w + 1 * NH * NH, hB);
    k_layer<<<nb_layer, 256>>>(hB, h0, conv_w + 2 * NH * NH, hA);
    k_layer<<<nb_layer, 256>>>(hA, h0, conv_w + 3 * NH * NH, hB);

    // fc2
    k_fc2<<<592, 320>>>(hB, fc2_w, fc2_b, out);
}

// round 3
// speedup vs baseline: 1.1085x; 1.1085x over previous
#include <cuda_runtime.h>
#include <cuda_fp16.h>

#define N_NODESC 100000
#define N_EDGESC 1600000
#define IN_CH    128
#define NH       64
#define NH2      32          // NH/2 half2 per node
#define OUT_CHC  40
#define ALPHA_F  0.1f

#define SCAN_CHUNK 1024
#define SCAN_NBLK  ((N_NODESC + SCAN_CHUNK - 1) / SCAN_CHUNK)   // 98

// ---------------- scratch (static device arrays; no runtime allocation) ----------------
__device__ int     g_is64;
__device__ int     g_deg[N_NODESC];
__device__ int     g_rowptr[N_NODESC + 1];
__device__ int     g_cursor[N_NODESC];
__device__ int     g_bsum[SCAN_NBLK];
__device__ int     g_boff[SCAN_NBLK];
__device__ int     g_row32[N_EDGESC];
__device__ int     g_col32[N_EDGESC];
__device__ int     g_src[N_EDGESC];
__device__ float   g_enorm[N_EDGESC];
__device__ float   g_dinv[N_NODESC];
__device__ float   g_h0[N_NODESC * NH];          // fp32 residual path
__device__ __half2 g_h016[N_NODESC * NH2];       // fp16 gather copies
__device__ __half2 g_hA16[N_NODESC * NH2];
__device__ __half2 g_hB16[N_NODESC * NH2];

// ---------------- dtype detect + zero degree (merged) ----------------
// JAX default config silently makes "int64" arrays int32. For little-endian
// int64 data every odd int32 word is a zero high-half; for int32 data odd
// words are random node ids.
__global__ void k_init(const int* __restrict__ ei) {
    int i = blockIdx.x * blockDim.x + threadIdx.x;
    if (i < N_NODESC) g_deg[i] = 0;
    if (blockIdx.x == 0 && threadIdx.x == 0) {
        int nz = 0;
        for (int j = 1; j < 512; j += 2) nz |= ei[j];
        g_is64 = (nz == 0) ? 1 : 0;
    }
}

// decode edge index -> int32 pair, histogram in-degree by col
__global__ void k_degree(const int* __restrict__ ei) {
    int e = blockIdx.x * blockDim.x + threadIdx.x;
    if (e >= N_EDGESC) return;
    int r, c;
    if (g_is64) {
        r = ei[2 * e];
        c = ei[2 * (N_EDGESC + e)];
    } else {
        r = ei[e];
        c = ei[N_EDGESC + e];
    }
    if ((unsigned)r >= N_NODESC) r = 0;
    if ((unsigned)c >= N_NODESC) c = 0;
    g_row32[e] = r;
    g_col32[e] = c;
    atomicAdd(&g_deg[c], 1);
}

// block sums for scan + dinv (merged: both just need deg)
__global__ void k_scan_bsum() {
    __shared__ int s[SCAN_CHUNK];
    int t = threadIdx.x;
    int i = blockIdx.x * SCAN_CHUNK + t;
    int d = (i < N_NODESC) ? g_deg[i] : 0;
    if (i < N_NODESC) g_dinv[i] = (d > 0) ? rsqrtf((float)d) : 0.0f;
    s[t] = d;
    __syncthreads();
    for (int off = SCAN_CHUNK / 2; off > 0; off >>= 1) {
        if (t < off) s[t] += s[t + off];
        __syncthreads();
    }
    if (t == 0) g_bsum[blockIdx.x] = s[0];
}

__global__ void k_scan_top() {
    __shared__ int s[128];
    int t = threadIdx.x;
    s[t] = (t < SCAN_NBLK) ? g_bsum[t] : 0;
    __syncthreads();
    if (t == 0) {
        int acc = 0;
        for (int b = 0; b < SCAN_NBLK; b++) { int v = s[b]; s[b] = acc; acc += v; }
        g_rowptr[N_NODESC] = N_EDGESC;
    }
    __syncthreads();
    if (t < SCAN_NBLK) g_boff[t] = s[t];
}

__global__ void k_scan_within() {
    __shared__ int s[SCAN_CHUNK];
    int t = threadIdx.x;
    int i = blockIdx.x * SCAN_CHUNK + t;
    int v = (i < N_NODESC) ? g_deg[i] : 0;
    s[t] = v;
    __syncthreads();
    for (int off = 1; off < SCAN_CHUNK; off <<= 1) {
        int x = (t >= off) ? s[t - off] : 0;
        __syncthreads();
        s[t] += x;
        __syncthreads();
    }
    int excl = s[t] - v + g_boff[blockIdx.x];
    if (i < N_NODESC) { g_rowptr[i] = excl; g_cursor[i] = excl; }
}

__global__ void k_scatter() {
    int e = blockIdx.x * blockDim.x + threadIdx.x;
    if (e >= N_EDGESC) return;
    int r = g_row32[e];
    int c = g_col32[e];
    float nm = g_dinv[r] * g_dinv[c];
    int pos = atomicAdd(&g_cursor[c], 1);
    if ((unsigned)pos < N_EDGESC) {
        g_src[pos]   = r;
        g_enorm[pos] = nm;
    }
}

// ---------------- fc1: h = relu(x @ W1^T + b1), x[N,128], W1[64,128] ----------------
// 2 nodes x 4 outputs per thread. block = 256 = 16 output-quads x 16 node-pairs.
#define FC1_NODES 32
__global__ __launch_bounds__(256, 4) void k_fc1(const float* __restrict__ x,
                                                const float* __restrict__ w,
                                                const float* __restrict__ b) {
    __shared__ float sW[IN_CH * NH];            // [k][j] transposed, 32 KB
    __shared__ float sX[FC1_NODES][IN_CH + 1];  // 16.5 KB
    __shared__ float sB[NH];
    for (int i = threadIdx.x; i < IN_CH * NH; i += 256) {
        int j = i >> 7, k = i & 127;            // w is [j][k]
        sW[k * NH + j] = w[i];
    }
    if (threadIdx.x < NH) sB[threadIdx.x] = b[threadIdx.x];
    __syncthreads();

    int jp = threadIdx.x & 15;                  // 4 outputs: 4*jp .. 4*jp+3
    int np = threadIdx.x >> 4;                  // node-pair 0..15
    int na = np * 2, nb = np * 2 + 1;
    const int ngroups = N_NODESC / FC1_NODES;   // 3125 exact

    for (int g = blockIdx.x; g < ngroups; g += gridDim.x) {
        int base = g * FC1_NODES;
        __syncthreads();
        for (int i = threadIdx.x; i < FC1_NODES * IN_CH; i += 256) {
            int n = i >> 7, k = i & 127;
            sX[n][k] = x[(long)(base + n) * IN_CH + k];
        }
        __syncthreads();

        float4 bb = *(const float4*)&sB[4 * jp];
        float4 aA = bb, aB = bb;
        #pragma unroll 8
        for (int k = 0; k < IN_CH; k++) {
            float4 wv = *(const float4*)&sW[k * NH + 4 * jp];
            float xa = sX[na][k];
            float xb = sX[nb][k];
            aA.x = fmaf(wv.x, xa, aA.x); aA.y = fmaf(wv.y, xa, aA.y);
            aA.z = fmaf(wv.z, xa, aA.z); aA.w = fmaf(wv.w, xa, aA.w);
            aB.x = fmaf(wv.x, xb, aB.x); aB.y = fmaf(wv.y, xb, aB.y);
            aB.z = fmaf(wv.z, xb, aB.z); aB.w = fmaf(wv.w, xb, aB.w);
        }
        aA.x = fmaxf(aA.x, 0.f); aA.y = fmaxf(aA.y, 0.f);
        aA.z = fmaxf(aA.z, 0.f); aA.w = fmaxf(aA.w, 0.f);
        aB.x = fmaxf(aB.x, 0.f); aB.y = fmaxf(aB.y, 0.f);
        aB.z = fmaxf(aB.z, 0.f); aB.w = fmaxf(aB.w, 0.f);
        *(float4*)&g_h0[(long)(base + na) * NH + 4 * jp] = aA;
        *(float4*)&g_h0[(long)(base + nb) * NH + 4 * jp] = aB;
        // fp16 copy for layer-1 gather
        g_h016[(base + na) * NH2 + 2 * jp]     = __floats2half2_rn(aA.x, aA.y);
        g_h016[(base + na) * NH2 + 2 * jp + 1] = __floats2half2_rn(aA.z, aA.w);
        g_h016[(base + nb) * NH2 + 2 * jp]     = __floats2half2_rn(aB.x, aB.y);
        g_h016[(base + nb) * NH2 + 2 * jp + 1] = __floats2half2_rn(aB.z, aB.w);
    }
}

// ---------------- fused GCN2 layer: fp16 gather + fp32 mix + 64x64 matmul + relu ----------------
// warp per node; block = 256 threads = 8 nodes; N divisible by 8 -> no bounds check
__global__ __launch_bounds__(256, 6) void k_layer(const __half2* __restrict__ hin,
                                                  const float* __restrict__ h0,
                                                  const float* __restrict__ W,
                                                  __half2* __restrict__ hout) {
    __shared__ float sW[NH * NH];           // 16 KB, W[k][j] row-major
    __shared__ float sMix[8][NH];
    for (int i = threadIdx.x; i < NH * NH; i += 256) sW[i] = W[i];
    __syncthreads();

    int warp = threadIdx.x >> 5;
    int lane = threadIdx.x & 31;
    int node = blockIdx.x * 8 + warp;

    int s = g_rowptr[node];
    int e = g_rowptr[node + 1];
    float ax = 0.f, ay = 0.f;
    #pragma unroll 4
    for (int i = s; i < e; i++) {
        int    src = __ldg(&g_src[i]);
        float  nm  = __ldg(&g_enorm[i]);
        float2 v   = __half22float2(__ldg(&hin[src * NH2 + lane]));
        ax = fmaf(nm, v.x, ax);
        ay = fmaf(nm, v.y, ay);
    }
    float2 h0v = *(const float2*)(h0 + (long)node * NH + lane * 2);
    float mx = fmaf(1.0f - ALPHA_F, ax, ALPHA_F * h0v.x);
    float my = fmaf(1.0f - ALPHA_F, ay, ALPHA_F * h0v.y);
    *(float2*)&sMix[warp][lane * 2] = make_float2(mx, my);
    __syncwarp();

    float o0 = 0.f, o1 = 0.f;
    #pragma unroll
    for (int k = 0; k < NH; k++) {
        float m = sMix[warp][k];
        float2 wv = *(const float2*)&sW[k * NH + lane * 2];
        o0 = fmaf(m, wv.x, o0);
        o1 = fmaf(m, wv.y, o1);
    }
    hout[node * NH2 + lane] = __floats2half2_rn(fmaxf(o0, 0.f), fmaxf(o1, 0.f));
}

// ---------------- fc2: out = h @ W2^T + b2, h[N,64] fp16, W2[40,64] ----------------
// block = 320 threads = 8 nodes x 40 outputs
__global__ __launch_bounds__(320, 4) void k_fc2(const __half2* __restrict__ hin,
                                                const float* __restrict__ w,
                                                const float* __restrict__ b,
                                                float* __restrict__ out) {
    __shared__ float sW[NH * OUT_CHC];      // [k][j] transposed, 10 KB
    __shared__ float sH[8][NH + 2];
    __shared__ float sB[OUT_CHC];
    for (int i = threadIdx.x; i < NH * OUT_CHC; i += 320) {
        int j = i >> 6, k = i & 63;         // w is [j][k]
        sW[k * OUT_CHC + j] = w[i];
    }
    if (threadIdx.x < OUT_CHC) sB[threadIdx.x] = b[threadIdx.x];
    __syncthreads();

    int tn = threadIdx.x / OUT_CHC;         // node 0..7
    int j  = threadIdx.x % OUT_CHC;
    const int ngroups = N_NODESC / 8;       // 12500 exact

    for (int g = blockIdx.x; g < ngroups; g += gridDim.x) {
        int base = g * 8;
        __syncthreads();
        for (int i = threadIdx.x; i < 8 * NH2; i += 320) {
            int n = i >> 5, k2 = i & 31;
            float2 v = __half22float2(hin[(base + n) * NH2 + k2]);
            sH[n][2 * k2]     = v.x;
            sH[n][2 * k2 + 1] = v.y;
        }
        __syncthreads();
        float acc = sB[j];
        #pragma unroll 8
        for (int k = 0; k < NH; k++)
            acc = fmaf(sH[tn][k], sW[k * OUT_CHC + j], acc);
        out[(long)(base + tn) * OUT_CHC + j] = acc;
    }
}

// ---------------- launch ----------------
extern "C" void kernel_launch(void* const* d_in, const int* in_sizes, int n_in,
                              void* d_out, int out_size) {
    const float* x      = (const float*)d_in[0];
    const int*   ei     = (const int*)d_in[1];   // int32 OR packed int64 (auto-detected)
    // d_in[2] = batch_graph (unused)
    const float* fc1_w  = (const float*)d_in[3];
    const float* fc1_b  = (const float*)d_in[4];
    const float* conv_w = (const float*)d_in[5];
    const float* fc2_w  = (const float*)d_in[6];
    const float* fc2_b  = (const float*)d_in[7];
    float*       out    = (float*)d_out;

    const int nb_nodes = (N_NODESC + 255) / 256;
    const int nb_edges = (N_EDGESC + 255) / 256;

    // preprocessing: detect+zero -> degree -> scan(+dinv) -> scatter
    k_init<<<nb_nodes, 256>>>(ei);
    k_degree<<<nb_edges, 256>>>(ei);
    k_scan_bsum<<<SCAN_NBLK, SCAN_CHUNK>>>();
    k_scan_top<<<1, 128>>>();
    k_scan_within<<<SCAN_NBLK, SCAN_CHUNK>>>();
    k_scatter<<<nb_edges, 256>>>();

    // fc1
    k_fc1<<<592, 256>>>(x, fc1_w, fc1_b);

    // resolve device pointers for static buffers
    float* h0; __half2* h016; __half2* hA16; __half2* hB16;
    cudaGetSymbolAddress((void**)&h0,   g_h0);
    cudaGetSymbolAddress((void**)&h016, g_h016);
    cudaGetSymbolAddress((void**)&hA16, g_hA16);
    cudaGetSymbolAddress((void**)&hB16, g_hB16);

    const int nb_layer = N_NODESC / 8;      // 12500 exact
    k_layer<<<nb_layer, 256>>>(h016, h0, conv_w + 0 * NH * NH, hA16);
    k_layer<<<nb_layer, 256>>>(hA16, h0, conv_w + 1 * NH * NH, hB16);
    k_layer<<<nb_layer, 256>>>(hB16, h0, conv_w + 2 * NH * NH, hA16);
    k_layer<<<nb_layer, 256>>>(hA16, h0, conv_w + 3 * NH * NH, hB16);

    // fc2
    k_fc2<<<592, 320>>>(hB16, fc2_w, fc2_b, out);
}

// round 4
// speedup vs baseline: 1.1952x; 1.0782x over previous
#include <cuda_runtime.h>
#include <cuda_fp16.h>

#define N_NODESC 100000
#define N_EDGESC 1600000
#define IN_CH    128
#define NH       64
#define NH2      32
#define OUT_CHC  40
#define ALPHA_F  0.1f

#define SCAN_CHUNK 1024
#define SCAN_NBLK  ((N_NODESC + SCAN_CHUNK - 1) / SCAN_CHUNK)   // 98

typedef unsigned long long u64b;

// ---------------- f32x2 packed-FMA helpers (bit-exact fp32, 2 MACs/instr) ----------------
__device__ __forceinline__ void ffma2(u64b& d, u64b a, u64b b) {
    asm("fma.rn.f32x2 %0, %1, %2, %0;" : "+l"(d) : "l"(a), "l"(b));
}
__device__ __forceinline__ u64b pack2(float x, float y) {
    u64b r; asm("mov.b64 %0, {%1, %2};" : "=l"(r) : "f"(x), "f"(y)); return r;
}
__device__ __forceinline__ float2 unpack2(u64b v) {
    float2 f; asm("mov.b64 {%0, %1}, %2;" : "=f"(f.x), "=f"(f.y) : "l"(v)); return f;
}

// ---------------- scratch ----------------
__device__ int    g_is64;
__device__ int    g_deg[N_NODESC];
__device__ int    g_rowptr[N_NODESC + 1];
__device__ int    g_cursor[N_NODESC];
__device__ int    g_bsum[SCAN_NBLK];
__device__ int    g_boff[SCAN_NBLK];
__device__ int    g_row32[N_EDGESC];
__device__ int    g_col32[N_EDGESC];
__device__ int2   g_edge[N_EDGESC];              // (src, norm-as-int) interleaved
__device__ float  g_dinv[N_NODESC];
__device__ float  g_h0[N_NODESC * NH];           // fp32 residual path
__device__ __half g_h016[N_NODESC * NH];         // fp16 gather copies
__device__ __half g_hA16[N_NODESC * NH];
__device__ __half g_hB16[N_NODESC * NH];

// ---------------- dtype detect + zero degree ----------------
__global__ void k_init(const int* __restrict__ ei) {
    int i = blockIdx.x * blockDim.x + threadIdx.x;
    if (i < N_NODESC) g_deg[i] = 0;
    if (blockIdx.x == 0 && threadIdx.x == 0) {
        int nz = 0;
        for (int j = 1; j < 512; j += 2) nz |= ei[j];
        g_is64 = (nz == 0) ? 1 : 0;
    }
}

__global__ void k_degree(const int* __restrict__ ei) {
    int e = blockIdx.x * blockDim.x + threadIdx.x;
    if (e >= N_EDGESC) return;
    int r, c;
    if (g_is64) { r = ei[2 * e]; c = ei[2 * (N_EDGESC + e)]; }
    else        { r = ei[e];     c = ei[N_EDGESC + e]; }
    if ((unsigned)r >= N_NODESC) r = 0;
    if ((unsigned)c >= N_NODESC) c = 0;
    g_row32[e] = r;
    g_col32[e] = c;
    atomicAdd(&g_deg[c], 1);
}

__global__ void k_scan_bsum() {
    __shared__ int s[SCAN_CHUNK];
    int t = threadIdx.x;
    int i = blockIdx.x * SCAN_CHUNK + t;
    int d = (i < N_NODESC) ? g_deg[i] : 0;
    if (i < N_NODESC) g_dinv[i] = (d > 0) ? rsqrtf((float)d) : 0.0f;
    s[t] = d;
    __syncthreads();
    for (int off = SCAN_CHUNK / 2; off > 0; off >>= 1) {
        if (t < off) s[t] += s[t + off];
        __syncthreads();
    }
    if (t == 0) g_bsum[blockIdx.x] = s[0];
}

__global__ void k_scan_top() {
    __shared__ int s[128];
    int t = threadIdx.x;
    s[t] = (t < SCAN_NBLK) ? g_bsum[t] : 0;
    __syncthreads();
    if (t == 0) {
        int acc = 0;
        for (int b = 0; b < SCAN_NBLK; b++) { int v = s[b]; s[b] = acc; acc += v; }
        g_rowptr[N_NODESC] = N_EDGESC;
    }
    __syncthreads();
    if (t < SCAN_NBLK) g_boff[t] = s[t];
}

__global__ void k_scan_within() {
    __shared__ int s[SCAN_CHUNK];
    int t = threadIdx.x;
    int i = blockIdx.x * SCAN_CHUNK + t;
    int v = (i < N_NODESC) ? g_deg[i] : 0;
    s[t] = v;
    __syncthreads();
    for (int off = 1; off < SCAN_CHUNK; off <<= 1) {
        int x = (t >= off) ? s[t - off] : 0;
        __syncthreads();
        s[t] += x;
        __syncthreads();
    }
    int excl = s[t] - v + g_boff[blockIdx.x];
    if (i < N_NODESC) { g_rowptr[i] = excl; g_cursor[i] = excl; }
}

__global__ void k_scatter() {
    int e = blockIdx.x * blockDim.x + threadIdx.x;
    if (e >= N_EDGESC) return;
    int r = g_row32[e];
    int c = g_col32[e];
    float nm = g_dinv[r] * g_dinv[c];
    int pos = atomicAdd(&g_cursor[c], 1);
    if ((unsigned)pos < N_EDGESC)
        g_edge[pos] = make_int2(r, __float_as_int(nm));
}

// ---------------- fc1: h = relu(x @ W1^T + b1), split-K f32x2 ----------------
// block = 128 = 16 jp x 8 node-pairs; thread: 2 nodes x 4 outputs (j = jp+16q)
#define FC1_NODES 16
#define SXS 132     // sX row stride (floats), 8B-aligned, bank-spread
#define SWS 130     // sW row stride: jp stride 520B mod 128 = 8 -> conflict-free
__global__ __launch_bounds__(128, 5) void k_fc1(const float* __restrict__ x,
                                                const float* __restrict__ w,
                                                const float* __restrict__ b) {
    __shared__ float sW[NH * SWS];          // [j][k], 33.3 KB
    __shared__ float sX[FC1_NODES * SXS];   // 8.4 KB
    __shared__ float sB[NH];
    for (int i = threadIdx.x; i < NH * IN_CH / 2; i += 128) {
        int j = i >> 6, kp = i & 63;        // w is [j][k] row-major
        *(float2*)&sW[j * SWS + 2 * kp] = *(const float2*)&w[j * IN_CH + 2 * kp];
    }
    if (threadIdx.x < NH) sB[threadIdx.x] = b[threadIdx.x];
    __syncthreads();

    int jp = threadIdx.x & 15;
    int np = threadIdx.x >> 4;              // 0..7
    int na = np * 2, nb = np * 2 + 1;
    const int ngroups = N_NODESC / FC1_NODES;   // 6250

    for (int g = blockIdx.x; g < ngroups; g += gridDim.x) {
        int base = g * FC1_NODES;
        __syncthreads();
        for (int i = threadIdx.x; i < FC1_NODES * IN_CH / 4; i += 128) {
            int n = i >> 5, k4 = (i & 31) * 4;
            *(float4*)&sX[n * SXS + k4] = *(const float4*)&x[(long)(base + n) * IN_CH + k4];
        }
        __syncthreads();

        u64b accA[4], accB[4];
        #pragma unroll
        for (int q = 0; q < 4; q++) {
            float bj = sB[jp + 16 * q];
            accA[q] = pack2(bj, 0.f);
            accB[q] = pack2(bj, 0.f);
        }
        #pragma unroll 8
        for (int kp = 0; kp < IN_CH / 2; kp++) {
            u64b xa = *(const u64b*)&sX[na * SXS + 2 * kp];
            u64b xb = *(const u64b*)&sX[nb * SXS + 2 * kp];
            #pragma unroll
            for (int q = 0; q < 4; q++) {
                u64b wv = *(const u64b*)&sW[(jp + 16 * q) * SWS + 2 * kp];
                ffma2(accA[q], xa, wv);
                ffma2(accB[q], xb, wv);
            }
        }
        #pragma unroll
        for (int q = 0; q < 4; q++) {
            int j = jp + 16 * q;
            float2 fa = unpack2(accA[q]);
            float2 fb = unpack2(accB[q]);
            float vA = fmaxf(fa.x + fa.y, 0.f);
            float vB = fmaxf(fb.x + fb.y, 0.f);
            g_h0[(long)(base + na) * NH + j] = vA;
            g_h0[(long)(base + nb) * NH + j] = vB;
            g_h016[(base + na) * NH + j] = __float2half(vA);
            g_h016[(base + nb) * NH + j] = __float2half(vB);
        }
    }
}

// ---------------- fused GCN2 layer ----------------
// warp per node; staged edge meta (1 LDS.64/edge); split-K f32x2 matmul
#define SWT 66      // transposed-W row stride
__global__ __launch_bounds__(256, 6) void k_layer(const __half* __restrict__ hin,
                                                  const float* __restrict__ h0,
                                                  const float* __restrict__ W,
                                                  __half* __restrict__ hout) {
    __shared__ float sWT[NH * SWT];         // [j][k], 16.9 KB
    __shared__ int2  sMeta[8][32];
    __shared__ float sMix[8][NH];
    for (int i = threadIdx.x; i < NH * NH; i += 256) {
        int k = i >> 6, j = i & 63;         // W is [k][j]
        sWT[j * SWT + k] = W[i];
    }
    __syncthreads();

    int warp = threadIdx.x >> 5;
    int lane = threadIdx.x & 31;
    int node = blockIdx.x * 8 + warp;
    const __half2* hin2 = (const __half2*)hin;

    int s = g_rowptr[node];
    int e = g_rowptr[node + 1];
    float ax = 0.f, ay = 0.f;
    for (int base = s; base < e; base += 32) {
        int rem = e - base;
        if (lane < rem) sMeta[warp][lane] = g_edge[base + lane];
        __syncwarp();
        if (rem >= 32) {
            #pragma unroll 8
            for (int j = 0; j < 32; j++) {
                int2 m = sMeta[warp][j];
                float2 v = __half22float2(__ldg(&hin2[m.x * NH2 + lane]));
                float nm = __int_as_float(m.y);
                ax = fmaf(nm, v.x, ax);
                ay = fmaf(nm, v.y, ay);
            }
        } else {
            for (int j = 0; j < rem; j++) {
                int2 m = sMeta[warp][j];
                float2 v = __half22float2(__ldg(&hin2[m.x * NH2 + lane]));
                float nm = __int_as_float(m.y);
                ax = fmaf(nm, v.x, ax);
                ay = fmaf(nm, v.y, ay);
            }
        }
        __syncwarp();
    }
    float2 h0v = *(const float2*)(h0 + (long)node * NH + lane * 2);
    float mx = fmaf(1.0f - ALPHA_F, ax, ALPHA_F * h0v.x);
    float my = fmaf(1.0f - ALPHA_F, ay, ALPHA_F * h0v.y);
    *(float2*)&sMix[warp][lane * 2] = make_float2(mx, my);
    __syncwarp();

    // matmul: lane owns outputs j=lane and j=lane+32; split-K over k-pairs
    u64b acc0 = 0ULL, acc1 = 0ULL;
    #pragma unroll 8
    for (int kp = 0; kp < NH / 2; kp++) {
        u64b m2 = *(const u64b*)&sMix[warp][2 * kp];
        u64b w0 = *(const u64b*)&sWT[lane * SWT + 2 * kp];
        u64b w1 = *(const u64b*)&sWT[(lane + 32) * SWT + 2 * kp];
        ffma2(acc0, m2, w0);
        ffma2(acc1, m2, w1);
    }
    float2 a0 = unpack2(acc0);
    float2 a1 = unpack2(acc1);
    hout[node * NH + lane]      = __float2half(fmaxf(a0.x + a0.y, 0.f));
    hout[node * NH + lane + 32] = __float2half(fmaxf(a1.x + a1.y, 0.f));
}

// ---------------- fc2: out = h @ W2^T + b2, split-K f32x2 ----------------
// block = 320 = 8 nodes x 40 outputs
#define SW2S 66
#define SH2S 66
__global__ __launch_bounds__(320, 4) void k_fc2(const __half* __restrict__ hin,
                                                const float* __restrict__ w,
                                                const float* __restrict__ b,
                                                float* __restrict__ out) {
    __shared__ float sW[OUT_CHC * SW2S];    // [j][k], 10.5 KB
    __shared__ float sH[8 * SH2S];
    __shared__ float sB[OUT_CHC];
    for (int i = threadIdx.x; i < OUT_CHC * NH / 2; i += 320) {
        int j = i >> 5, kp = i & 31;        // w is [j][k]
        *(float2*)&sW[j * SW2S + 2 * kp] = *(const float2*)&w[j * NH + 2 * kp];
    }
    if (threadIdx.x < OUT_CHC) sB[threadIdx.x] = b[threadIdx.x];
    __syncthreads();

    int tn = threadIdx.x / OUT_CHC;         // node 0..7
    int j  = threadIdx.x % OUT_CHC;
    const int ngroups = N_NODESC / 8;       // 12500
    const __half2* hin2 = (const __half2*)hin;

    for (int g = blockIdx.x; g < ngroups; g += gridDim.x) {
        int base = g * 8;
        __syncthreads();
        for (int i = threadIdx.x; i < 8 * NH2; i += 320) {
            int n = i >> 5, k2 = i & 31;
            float2 v = __half22float2(hin2[(base + n) * NH2 + k2]);
            *(float2*)&sH[n * SH2S + 2 * k2] = v;
        }
        __syncthreads();
        u64b acc = pack2(sB[j], 0.f);
        #pragma unroll 8
        for (int kp = 0; kp < NH / 2; kp++) {
            u64b a = *(const u64b*)&sH[tn * SH2S + 2 * kp];
            u64b wv = *(const u64b*)&sW[j * SW2S + 2 * kp];
            ffma2(acc, a, wv);
        }
        float2 f = unpack2(acc);
        out[(long)(base + tn) * OUT_CHC + j] = f.x + f.y;
    }
}

// ---------------- launch ----------------
extern "C" void kernel_launch(void* const* d_in, const int* in_sizes, int n_in,
                              void* d_out, int out_size) {
    const float* x      = (const float*)d_in[0];
    const int*   ei     = (const int*)d_in[1];
    const float* fc1_w  = (const float*)d_in[3];
    const float* fc1_b  = (const float*)d_in[4];
    const float* conv_w = (const float*)d_in[5];
    const float* fc2_w  = (const float*)d_in[6];
    const float* fc2_b  = (const float*)d_in[7];
    float*       out    = (float*)d_out;

    const int nb_nodes = (N_NODESC + 255) / 256;
    const int nb_edges = (N_EDGESC + 255) / 256;

    k_init<<<nb_nodes, 256>>>(ei);          // slot 0
    k_degree<<<nb_edges, 256>>>(ei);        // slot 1
    k_scan_bsum<<<SCAN_NBLK, SCAN_CHUNK>>>(); // slot 2
    k_fc1<<<1184, 128>>>(x, fc1_w, fc1_b);  // slot 3 (profiled by ncu -s)
    k_scan_top<<<1, 128>>>();
    k_scan_within<<<SCAN_NBLK, SCAN_CHUNK>>>();
    k_scatter<<<nb_edges, 256>>>();

    float* h0; __half* h016; __half* hA16; __half* hB16;
    cudaGetSymbolAddress((void**)&h0,   g_h0);
    cudaGetSymbolAddress((void**)&h016, g_h016);
    cudaGetSymbolAddress((void**)&hA16, g_hA16);
    cudaGetSymbolAddress((void**)&hB16, g_hB16);

    const int nb_layer = N_NODESC / 8;      // 12500
    k_layer<<<nb_layer, 256>>>(h016, h0, conv_w + 0 * NH * NH, hA16);
    k_layer<<<nb_layer, 256>>>(hA16, h0, conv_w + 1 * NH * NH, hB16);
    k_layer<<<nb_layer, 256>>>(hB16, h0, conv_w + 2 * NH * NH, hA16);
    k_layer<<<nb_layer, 256>>>(hA16, h0, conv_w + 3 * NH * NH, hB16);

    k_fc2<<<592, 320>>>(hB16, fc2_w, fc2_b, out);
}

// round 5
// speedup vs baseline: 1.3342x; 1.1162x over previous
#include <cuda_runtime.h>
#include <cuda_fp16.h>

#define N_NODESC 100000
#define N_EDGESC 1600000
#define IN_CH    128
#define NH       64
#define NH2      32
#define OUT_CHC  40

#define SCAN_CHUNK 1024
#define SCAN_NBLK  ((N_NODESC + SCAN_CHUNK - 1) / SCAN_CHUNK)   // 98

typedef unsigned long long u64b;

// ---------------- f32x2 packed helpers (bit-exact fp32, 2 MACs/instr) ----------------
__device__ __forceinline__ void ffma2(u64b& d, u64b a, u64b b) {
    asm("fma.rn.f32x2 %0, %1, %2, %0;" : "+l"(d) : "l"(a), "l"(b));
}
__device__ __forceinline__ float2 unpack2(u64b v) {
    float2 f; asm("mov.b64 {%0, %1}, %2;" : "=f"(f.x), "=f"(f.y) : "l"(v)); return f;
}
union F4U { float4 v; u64b d[2]; };

// ---------------- scratch ----------------
__device__ int     g_is64;
__device__ int     g_deg[N_NODESC];
__device__ int     g_rowptr[N_NODESC + 1];
__device__ int     g_cursor[N_NODESC];
__device__ int     g_bsum[SCAN_NBLK];
__device__ int     g_boff[SCAN_NBLK];
__device__ int     g_row32[N_EDGESC];
__device__ int     g_col32[N_EDGESC];
__device__ int     g_src[N_EDGESC];
__device__ float   g_dinv[N_NODESC];
__device__ float   g_h0[N_NODESC * NH];          // fp32 residual path (unscaled)
__device__ __half2 g_h016[N_NODESC * NH2];       // fp16, pre-scaled by dinv[node]
__device__ __half2 g_hA16[N_NODESC * NH2];
__device__ __half2 g_hB16[N_NODESC * NH2];

// ---------------- dtype detect + zero degree ----------------
__global__ void k_init(const int* __restrict__ ei) {
    int i = blockIdx.x * blockDim.x + threadIdx.x;
    if (i < N_NODESC) g_deg[i] = 0;
    if (blockIdx.x == 0 && threadIdx.x == 0) {
        int nz = 0;
        for (int j = 1; j < 512; j += 2) nz |= ei[j];
        g_is64 = (nz == 0) ? 1 : 0;
    }
}

// 2 edges per thread
__global__ void k_degree(const int* __restrict__ ei) {
    int t = blockIdx.x * blockDim.x + threadIdx.x;
    if (t >= N_EDGESC / 2) return;
    int r0, c0, r1, c1;
    if (g_is64) {
        int4 rr = __ldg((const int4*)&ei[4 * t]);
        int4 cc = __ldg((const int4*)&ei[2 * N_EDGESC + 4 * t]);
        r0 = rr.x; r1 = rr.z; c0 = cc.x; c1 = cc.z;
    } else {
        int2 rr = __ldg((const int2*)&ei[2 * t]);
        int2 cc = __ldg((const int2*)&ei[N_EDGESC + 2 * t]);
        r0 = rr.x; r1 = rr.y; c0 = cc.x; c1 = cc.y;
    }
    if ((unsigned)r0 >= N_NODESC) r0 = 0;
    if ((unsigned)r1 >= N_NODESC) r1 = 0;
    if ((unsigned)c0 >= N_NODESC) c0 = 0;
    if ((unsigned)c1 >= N_NODESC) c1 = 0;
    *(int2*)&g_row32[2 * t] = make_int2(r0, r1);
    *(int2*)&g_col32[2 * t] = make_int2(c0, c1);
    atomicAdd(&g_deg[c0], 1);
    atomicAdd(&g_deg[c1], 1);
}

__global__ void k_scan_bsum() {
    __shared__ int s[SCAN_CHUNK];
    int t = threadIdx.x;
    int i = blockIdx.x * SCAN_CHUNK + t;
    int d = (i < N_NODESC) ? g_deg[i] : 0;
    if (i < N_NODESC) g_dinv[i] = (d > 0) ? rsqrtf((float)d) : 0.0f;
    s[t] = d;
    __syncthreads();
    for (int off = SCAN_CHUNK / 2; off > 0; off >>= 1) {
        if (t < off) s[t] += s[t + off];
        __syncthreads();
    }
    if (t == 0) g_bsum[blockIdx.x] = s[0];
}

__global__ void k_scan_top() {
    __shared__ int s[128];
    int t = threadIdx.x;
    s[t] = (t < SCAN_NBLK) ? g_bsum[t] : 0;
    __syncthreads();
    if (t == 0) {
        int acc = 0;
        for (int b = 0; b < SCAN_NBLK; b++) { int v = s[b]; s[b] = acc; acc += v; }
        g_rowptr[N_NODESC] = N_EDGESC;
    }
    __syncthreads();
    if (t < SCAN_NBLK) g_boff[t] = s[t];
}

__global__ void k_scan_within() {
    __shared__ int s[SCAN_CHUNK];
    int t = threadIdx.x;
    int i = blockIdx.x * SCAN_CHUNK + t;
    int v = (i < N_NODESC) ? g_deg[i] : 0;
    s[t] = v;
    __syncthreads();
    for (int off = 1; off < SCAN_CHUNK; off <<= 1) {
        int x = (t >= off) ? s[t - off] : 0;
        __syncthreads();
        s[t] += x;
        __syncthreads();
    }
    int excl = s[t] - v + g_boff[blockIdx.x];
    if (i < N_NODESC) { g_rowptr[i] = excl; g_cursor[i] = excl; }
}

// 2 edges per thread; src index only (norm folded into fp16 values)
__global__ void k_scatter() {
    int t = blockIdx.x * blockDim.x + threadIdx.x;
    if (t >= N_EDGESC / 2) return;
    int2 rr = *(const int2*)&g_row32[2 * t];
    int2 cc = *(const int2*)&g_col32[2 * t];
    int p0 = atomicAdd(&g_cursor[cc.x], 1);
    if ((unsigned)p0 < N_EDGESC) g_src[p0] = rr.x;
    int p1 = atomicAdd(&g_cursor[cc.y], 1);
    if ((unsigned)p1 < N_EDGESC) g_src[p1] = rr.y;
}

// ---------------- fc1: h = relu(x @ W1^T + b1); lane=node, 8 j per lane ----------------
// block 256 = 8 warps; warp w owns j in [8w, 8w+8); tile = 32 nodes (lane = node).
// sX rotation-swizzled float4 rows -> conflict-free LDS.128 spread reads.
__global__ __launch_bounds__(256) void k_fc1(const float* __restrict__ x,
                                             const float* __restrict__ w,
                                             const float* __restrict__ b) {
    __shared__ float  sW[NH * IN_CH];   // 32 KB, [j][k] (broadcast reads)
    __shared__ float4 sX[32 * 32];      // 16 KB, [node][unit'], unit' = (u + node) & 31
    for (int i = threadIdx.x; i < NH * IN_CH; i += 256) sW[i] = w[i];

    int warp = threadIdx.x >> 5, lane = threadIdx.x & 31;
    int j0 = warp * 8;
    float4 b0 = __ldg((const float4*)&b[j0]);
    float4 b1 = __ldg((const float4*)&b[j0 + 4]);
    float bias[8] = {b0.x, b0.y, b0.z, b0.w, b1.x, b1.y, b1.z, b1.w};

    const int ntiles = N_NODESC / 32;   // 3125
    for (int tile = blockIdx.x; tile < ntiles; tile += gridDim.x) {
        int base = tile * 32;
        __syncthreads();
        {   // stage x, rotated
            int n = threadIdx.x >> 3;
            int u0 = threadIdx.x & 7;
            #pragma unroll
            for (int it = 0; it < 4; it++) {
                int u = u0 + 8 * it;
                float4 v = __ldg((const float4*)&x[(long)(base + n) * IN_CH + u * 4]);
                sX[n * 32 + ((u + n) & 31)] = v;
            }
        }
        __syncthreads();

        u64b acc[8];
        #pragma unroll
        for (int q = 0; q < 8; q++) acc[q] = 0ULL;

        #pragma unroll 4
        for (int kq = 0; kq < 32; kq++) {
            F4U xv; xv.v = sX[lane * 32 + ((kq + lane) & 31)];
            #pragma unroll
            for (int q = 0; q < 8; q++) {
                F4U wv; wv.v = *(const float4*)&sW[(j0 + q) * IN_CH + kq * 4];
                ffma2(acc[q], xv.d[0], wv.d[0]);
                ffma2(acc[q], xv.d[1], wv.d[1]);
            }
        }

        int node = base + lane;
        float dv = g_dinv[node];
        float r[8];
        #pragma unroll
        for (int q = 0; q < 8; q++) {
            float2 f = unpack2(acc[q]);
            r[q] = fmaxf(f.x + f.y + bias[q], 0.f);
        }
        *(float4*)&g_h0[(long)node * NH + j0]     = make_float4(r[0], r[1], r[2], r[3]);
        *(float4*)&g_h0[(long)node * NH + j0 + 4] = make_float4(r[4], r[5], r[6], r[7]);
        __half2 hh[4];
        #pragma unroll
        for (int q = 0; q < 4; q++)
            hh[q] = __floats2half2_rn(r[2 * q] * dv, r[2 * q + 1] * dv);
        *(uint2*)&g_h016[node * NH2 + (j0 >> 1)]     = *(uint2*)&hh[0];
        *(uint2*)&g_h016[node * NH2 + (j0 >> 1) + 2] = *(uint2*)&hh[2];
    }
}

// ---------------- fused GCN2 layer: 64-node blocks ----------------
// Phase 1 (gather): warp w gathers nodes [64b + 8w, +8): scaled-fp16 gather, fp32 acc,
//   mix with h0, store transposed to sMixT[kp][n].
// Phase 2 (matmul): thread (j2 = lane, nq = warp): 8 nodes x 2 adjacent j, packed-W
//   rotation-swizzled LDS.128 (512B fully used), f32x2 k-split accumulate.
__global__ __launch_bounds__(256) void k_layer(const __half2* __restrict__ hin2,
                                               const float* __restrict__ h0,
                                               const float* __restrict__ W,
                                               __half2* __restrict__ hout2,
                                               int scale_out) {
    __shared__ float4 sW4[32 * 32];     // 16 KB: [j2][(kp+j2)&31] = {W[2kp][2j2],W[2kp+1][2j2],W[2kp][2j2+1],W[2kp+1][2j2+1]}
    __shared__ float2 sMixT[32 * 66];   // 16.9 KB: [kp][n], row stride 66

    for (int i = threadIdx.x; i < NH * NH; i += 256) {
        int k = i >> 6, j = i & 63;     // W row-major [k][j]
        int j2 = j >> 1, kp = k >> 1;
        int sel = ((j & 1) << 1) | (k & 1);
        ((float*)sW4)[j2 * 128 + (((kp + j2) & 31) << 2) + sel] = W[i];
    }

    int warp = threadIdx.x >> 5, lane = threadIdx.x & 31;
    int nodebase = blockIdx.x * 64;

    // gather 8 nodes per warp
    for (int m = 0; m < 8; m++) {
        int nl = warp * 8 + m;
        int node = nodebase + nl;
        float ax0 = 0.f, ay0 = 0.f, ax1 = 0.f, ay1 = 0.f;
        float mx = 0.f, my = 0.f;
        if (node < N_NODESC) {
            int s = g_rowptr[node], e = g_rowptr[node + 1];
            int i = s;
            for (; i + 4 <= e; i += 4) {
                int s0 = __ldg(&g_src[i]);
                int s1 = __ldg(&g_src[i + 1]);
                int s2 = __ldg(&g_src[i + 2]);
                int s3 = __ldg(&g_src[i + 3]);
                float2 v0 = __half22float2(__ldg(&hin2[s0 * NH2 + lane]));
                float2 v1 = __half22float2(__ldg(&hin2[s1 * NH2 + lane]));
                float2 v2 = __half22float2(__ldg(&hin2[s2 * NH2 + lane]));
                float2 v3 = __half22float2(__ldg(&hin2[s3 * NH2 + lane]));
                ax0 += v0.x; ay0 += v0.y;
                ax1 += v1.x; ay1 += v1.y;
                ax0 += v2.x; ay0 += v2.y;
                ax1 += v3.x; ay1 += v3.y;
            }
            for (; i < e; i++) {
                int s0 = __ldg(&g_src[i]);
                float2 v0 = __half22float2(__ldg(&hin2[s0 * NH2 + lane]));
                ax0 += v0.x; ay0 += v0.y;
            }
            float ax = ax0 + ax1, ay = ay0 + ay1;
            float2 h0v = *(const float2*)&h0[(long)node * NH + lane * 2];
            float dv = g_dinv[node];
            mx = fmaf(0.9f * dv, ax, 0.1f * h0v.x);
            my = fmaf(0.9f * dv, ay, 0.1f * h0v.y);
        }
        sMixT[lane * 66 + nl] = make_float2(mx, my);
    }
    __syncthreads();

    // matmul
    int j2 = lane, nq = warp;
    u64b a0[8], a1[8];
    #pragma unroll
    for (int n = 0; n < 8; n++) { a0[n] = 0ULL; a1[n] = 0ULL; }

    #pragma unroll 4
    for (int kp = 0; kp < 32; kp++) {
        F4U wv; wv.v = sW4[j2 * 32 + ((kp + j2) & 31)];
        const float2* mrow = &sMixT[kp * 66 + nq * 8];
        #pragma unroll
        for (int p = 0; p < 4; p++) {
            F4U mp; mp.v = *(const float4*)&mrow[2 * p];
            ffma2(a0[2 * p],     mp.d[0], wv.d[0]);
            ffma2(a1[2 * p],     mp.d[0], wv.d[1]);
            ffma2(a0[2 * p + 1], mp.d[1], wv.d[0]);
            ffma2(a1[2 * p + 1], mp.d[1], wv.d[1]);
        }
    }

    #pragma unroll
    for (int n = 0; n < 8; n++) {
        int node = nodebase + nq * 8 + n;
        if (node < N_NODESC) {
            float2 f0 = unpack2(a0[n]);
            float2 f1 = unpack2(a1[n]);
            float o0 = fmaxf(f0.x + f0.y, 0.f);
            float o1 = fmaxf(f1.x + f1.y, 0.f);
            float sc = scale_out ? g_dinv[node] : 1.0f;
            hout2[node * NH2 + j2] = __floats2half2_rn(o0 * sc, o1 * sc);
        }
    }
}

// ---------------- fc2: out = h @ W2^T + b2, split-K f32x2 ----------------
#define SW2S 66
#define SH2S 66
__global__ __launch_bounds__(320, 4) void k_fc2(const __half2* __restrict__ hin2,
                                                const float* __restrict__ w,
                                                const float* __restrict__ b,
                                                float* __restrict__ out) {
    __shared__ float sW[OUT_CHC * SW2S];
    __shared__ float sH[8 * SH2S];
    __shared__ float sB[OUT_CHC];
    for (int i = threadIdx.x; i < OUT_CHC * NH / 2; i += 320) {
        int j = i >> 5, kp = i & 31;
        *(float2*)&sW[j * SW2S + 2 * kp] = *(const float2*)&w[j * NH + 2 * kp];
    }
    if (threadIdx.x < OUT_CHC) sB[threadIdx.x] = b[threadIdx.x];
    __syncthreads();

    int tn = threadIdx.x / OUT_CHC;
    int j  = threadIdx.x % OUT_CHC;
    const int ngroups = N_NODESC / 8;

    for (int g = blockIdx.x; g < ngroups; g += gridDim.x) {
        int base = g * 8;
        __syncthreads();
        for (int i = threadIdx.x; i < 8 * NH2; i += 320) {
            int n = i >> 5, k2 = i & 31;
            float2 v = __half22float2(hin2[(base + n) * NH2 + k2]);
            *(float2*)&sH[n * SH2S + 2 * k2] = v;
        }
        __syncthreads();
        u64b acc = 0ULL;
        #pragma unroll 8
        for (int kp = 0; kp < NH / 2; kp++) {
            u64b a  = *(const u64b*)&sH[tn * SH2S + 2 * kp];
            u64b wv = *(const u64b*)&sW[j * SW2S + 2 * kp];
            ffma2(acc, a, wv);
        }
        float2 f = unpack2(acc);
        out[(long)(base + tn) * OUT_CHC + j] = f.x + f.y + sB[j];
    }
}

// ---------------- launch ----------------
extern "C" void kernel_launch(void* const* d_in, const int* in_sizes, int n_in,
                              void* d_out, int out_size) {
    const float* x      = (const float*)d_in[0];
    const int*   ei     = (const int*)d_in[1];
    const float* fc1_w  = (const float*)d_in[3];
    const float* fc1_b  = (const float*)d_in[4];
    const float* conv_w = (const float*)d_in[5];
    const float* fc2_w  = (const float*)d_in[6];
    const float* fc2_b  = (const float*)d_in[7];
    float*       out    = (float*)d_out;

    const int nb_nodes  = (N_NODESC + 255) / 256;
    const int nb_epairs = (N_EDGESC / 2 + 255) / 256;

    k_init<<<nb_nodes, 256>>>(ei);              // 0
    k_degree<<<nb_epairs, 256>>>(ei);           // 1
    k_scan_bsum<<<SCAN_NBLK, SCAN_CHUNK>>>();   // 2 (also dinv)
    k_fc1<<<592, 256>>>(x, fc1_w, fc1_b);       // 3 (profiled slot)
    k_scan_top<<<1, 128>>>();
    k_scan_within<<<SCAN_NBLK, SCAN_CHUNK>>>();
    k_scatter<<<nb_epairs, 256>>>();

    float* h0; __half2* h016; __half2* hA16; __half2* hB16;
    cudaGetSymbolAddress((void**)&h0,   g_h0);
    cudaGetSymbolAddress((void**)&h016, g_h016);
    cudaGetSymbolAddress((void**)&hA16, g_hA16);
    cudaGetSymbolAddress((void**)&hB16, g_hB16);

    const int nb_layer = (N_NODESC + 63) / 64;  // 1563
    k_layer<<<nb_layer, 256>>>(h016, h0, conv_w + 0 * NH * NH, hA16, 1);
    k_layer<<<nb_layer, 256>>>(hA16, h0, conv_w + 1 * NH * NH, hB16, 1);
    k_layer<<<nb_layer, 256>>>(hB16, h0, conv_w + 2 * NH * NH, hA16, 1);
    k_layer<<<nb_layer, 256>>>(hA16, h0, conv_w + 3 * NH * NH, hB16, 0);

    k_fc2<<<592, 320>>>(hB16, fc2_w, fc2_b, out);
}

// round 6
// speedup vs baseline: 1.3766x; 1.0318x over previous
#include <cuda_runtime.h>
#include <cuda_fp16.h>

#define N_NODESC 100000
#define N_EDGESC 1600000
#define IN_CH    128
#define NH       64
#define NH2      32
#define OUT_CHC  40

#define SCAN_CHUNK 1024
#define SCAN_NBLK  ((N_NODESC + SCAN_CHUNK - 1) / SCAN_CHUNK)   // 98

typedef unsigned long long u64b;

// ---------------- f32x2 packed helpers (bit-exact fp32, 2 MACs/instr) ----------------
__device__ __forceinline__ void ffma2(u64b& d, u64b a, u64b b) {
    asm("fma.rn.f32x2 %0, %1, %2, %0;" : "+l"(d) : "l"(a), "l"(b));
}
__device__ __forceinline__ float2 unpack2(u64b v) {
    float2 f; asm("mov.b64 {%0, %1}, %2;" : "=f"(f.x), "=f"(f.y) : "l"(v)); return f;
}
union F4U { float4 v; u64b d[2]; };

// ---------------- scratch ----------------
__device__ int     g_is64;
__device__ int     g_deg[N_NODESC];
__device__ int     g_rowptr[N_NODESC + 1];
__device__ int     g_cursor[N_NODESC];
__device__ int     g_bsum[SCAN_NBLK];
__device__ int     g_boff[SCAN_NBLK];
__device__ int     g_row32[N_EDGESC];
__device__ int     g_col32[N_EDGESC];
__device__ int     g_src[N_EDGESC];
__device__ float   g_dinv[N_NODESC];
__device__ float   g_h0[N_NODESC * NH];          // fp32 residual path (unscaled)
__device__ __half2 g_h016[N_NODESC * NH2];       // fp16, pre-scaled by dinv[node]
__device__ __half2 g_hA16[N_NODESC * NH2];
__device__ __half2 g_hB16[N_NODESC * NH2];

// ---------------- dtype detect + zero degree ----------------
__global__ void k_init(const int* __restrict__ ei) {
    int i = blockIdx.x * blockDim.x + threadIdx.x;
    if (i < N_NODESC) g_deg[i] = 0;
    if (blockIdx.x == 0 && threadIdx.x == 0) {
        int nz = 0;
        for (int j = 1; j < 512; j += 2) nz |= ei[j];
        g_is64 = (nz == 0) ? 1 : 0;
    }
}

// 2 edges per thread
__global__ void k_degree(const int* __restrict__ ei) {
    int t = blockIdx.x * blockDim.x + threadIdx.x;
    if (t >= N_EDGESC / 2) return;
    int r0, c0, r1, c1;
    if (g_is64) {
        int4 rr = __ldg((const int4*)&ei[4 * t]);
        int4 cc = __ldg((const int4*)&ei[2 * N_EDGESC + 4 * t]);
        r0 = rr.x; r1 = rr.z; c0 = cc.x; c1 = cc.z;
    } else {
        int2 rr = __ldg((const int2*)&ei[2 * t]);
        int2 cc = __ldg((const int2*)&ei[N_EDGESC + 2 * t]);
        r0 = rr.x; r1 = rr.y; c0 = cc.x; c1 = cc.y;
    }
    if ((unsigned)r0 >= N_NODESC) r0 = 0;
    if ((unsigned)r1 >= N_NODESC) r1 = 0;
    if ((unsigned)c0 >= N_NODESC) c0 = 0;
    if ((unsigned)c1 >= N_NODESC) c1 = 0;
    *(int2*)&g_row32[2 * t] = make_int2(r0, r1);
    *(int2*)&g_col32[2 * t] = make_int2(c0, c1);
    atomicAdd(&g_deg[c0], 1);
    atomicAdd(&g_deg[c1], 1);
}

__global__ void k_scan_bsum() {
    __shared__ int s[SCAN_CHUNK];
    int t = threadIdx.x;
    int i = blockIdx.x * SCAN_CHUNK + t;
    int d = (i < N_NODESC) ? g_deg[i] : 0;
    if (i < N_NODESC) g_dinv[i] = (d > 0) ? rsqrtf((float)d) : 0.0f;
    s[t] = d;
    __syncthreads();
    for (int off = SCAN_CHUNK / 2; off > 0; off >>= 1) {
        if (t < off) s[t] += s[t + off];
        __syncthreads();
    }
    if (t == 0) g_bsum[blockIdx.x] = s[0];
}

__global__ void k_scan_top() {
    __shared__ int s[128];
    int t = threadIdx.x;
    s[t] = (t < SCAN_NBLK) ? g_bsum[t] : 0;
    __syncthreads();
    if (t == 0) {
        int acc = 0;
        for (int b = 0; b < SCAN_NBLK; b++) { int v = s[b]; s[b] = acc; acc += v; }
        g_rowptr[N_NODESC] = N_EDGESC;
    }
    __syncthreads();
    if (t < SCAN_NBLK) g_boff[t] = s[t];
}

__global__ void k_scan_within() {
    __shared__ int s[SCAN_CHUNK];
    int t = threadIdx.x;
    int i = blockIdx.x * SCAN_CHUNK + t;
    int v = (i < N_NODESC) ? g_deg[i] : 0;
    s[t] = v;
    __syncthreads();
    for (int off = 1; off < SCAN_CHUNK; off <<= 1) {
        int x = (t >= off) ? s[t - off] : 0;
        __syncthreads();
        s[t] += x;
        __syncthreads();
    }
    int excl = s[t] - v + g_boff[blockIdx.x];
    if (i < N_NODESC) { g_rowptr[i] = excl; g_cursor[i] = excl; }
}

// 2 edges per thread; src index only (norm folded into fp16 values)
__global__ void k_scatter() {
    int t = blockIdx.x * blockDim.x + threadIdx.x;
    if (t >= N_EDGESC / 2) return;
    int2 rr = *(const int2*)&g_row32[2 * t];
    int2 cc = *(const int2*)&g_col32[2 * t];
    int p0 = atomicAdd(&g_cursor[cc.x], 1);
    if ((unsigned)p0 < N_EDGESC) g_src[p0] = rr.x;
    int p1 = atomicAdd(&g_cursor[cc.y], 1);
    if ((unsigned)p1 < N_EDGESC) g_src[p1] = rr.y;
}

// ---------------- fc1: h = relu(x @ W1^T + b1) ----------------
// block 256 = 8 warps; warp w owns j in [8w, 8w+8); tile = 64 nodes.
// Thread: 2 nodes (lane, lane+32) x 8 outputs -> 16 f32x2 accumulators.
// Per kq: 2 spread x LDS.128 + 8 broadcast W LDS.128 = 16 phases / 32 FFMA2
// -> SM crossbar load (8w x 16) == per-SMSP FMA load (2w x 32 x 2). Balanced.
#define FC1_TILE 64
__global__ __launch_bounds__(256) void k_fc1(const float* __restrict__ x,
                                             const float* __restrict__ w,
                                             const float* __restrict__ b) {
    __shared__ float  sW[NH * IN_CH];       // 32 KB, [j][k] (broadcast reads)
    __shared__ float4 sX[FC1_TILE * 32];    // 32 KB, [node][(u+node)&31]
    for (int i = threadIdx.x; i < NH * IN_CH; i += 256) sW[i] = w[i];

    int warp = threadIdx.x >> 5, lane = threadIdx.x & 31;
    int j0 = warp * 8;
    float4 b0 = __ldg((const float4*)&b[j0]);
    float4 b1 = __ldg((const float4*)&b[j0 + 4]);
    float bias[8] = {b0.x, b0.y, b0.z, b0.w, b1.x, b1.y, b1.z, b1.w};

    const int ntiles = (N_NODESC + FC1_TILE - 1) / FC1_TILE;    // 1563
    for (int tile = blockIdx.x; tile < ntiles; tile += gridDim.x) {
        int base = tile * FC1_TILE;
        __syncthreads();
        {   // stage 64 nodes, rotated rows; clamp OOB rows to node 0 of tile
            int n = threadIdx.x >> 2;           // 0..63
            int u0 = threadIdx.x & 3;
            long row = (base + n < N_NODESC) ? (long)(base + n) : (long)base;
            #pragma unroll
            for (int it = 0; it < 8; it++) {
                int u = u0 + 4 * it;
                float4 v = __ldg((const float4*)&x[row * IN_CH + u * 4]);
                sX[n * 32 + ((u + n) & 31)] = v;
            }
        }
        __syncthreads();

        int nA = lane, nB = lane + 32;
        u64b accA[8], accB[8];
        #pragma unroll
        for (int q = 0; q < 8; q++) { accA[q] = 0ULL; accB[q] = 0ULL; }

        #pragma unroll 4
        for (int kq = 0; kq < 32; kq++) {
            F4U xa; xa.v = sX[nA * 32 + ((kq + nA) & 31)];
            F4U xb; xb.v = sX[nB * 32 + ((kq + nB) & 31)];
            #pragma unroll
            for (int q = 0; q < 8; q++) {
                F4U wv; wv.v = *(const float4*)&sW[(j0 + q) * IN_CH + kq * 4];
                ffma2(accA[q], xa.d[0], wv.d[0]);
                ffma2(accA[q], xa.d[1], wv.d[1]);
                ffma2(accB[q], xb.d[0], wv.d[0]);
                ffma2(accB[q], xb.d[1], wv.d[1]);
            }
        }

        #pragma unroll
        for (int half = 0; half < 2; half++) {
            int node = base + (half ? nB : nA);
            if (node >= N_NODESC) continue;
            u64b* acc = half ? accB : accA;
            float dv = g_dinv[node];
            float r[8];
            #pragma unroll
            for (int q = 0; q < 8; q++) {
                float2 f = unpack2(acc[q]);
                r[q] = fmaxf(f.x + f.y + bias[q], 0.f);
            }
            *(float4*)&g_h0[(long)node * NH + j0]     = make_float4(r[0], r[1], r[2], r[3]);
            *(float4*)&g_h0[(long)node * NH + j0 + 4] = make_float4(r[4], r[5], r[6], r[7]);
            __half2 hh[4];
            #pragma unroll
            for (int q = 0; q < 4; q++)
                hh[q] = __floats2half2_rn(r[2 * q] * dv, r[2 * q + 1] * dv);
            *(uint2*)&g_h016[node * NH2 + (j0 >> 1)]     = *(uint2*)&hh[0];
            *(uint2*)&g_h016[node * NH2 + (j0 >> 1) + 2] = *(uint2*)&hh[2];
        }
    }
}

// ---------------- fused GCN2 layer: 64-node blocks ----------------
__global__ __launch_bounds__(256) void k_layer(const __half2* __restrict__ hin2,
                                               const float* __restrict__ h0,
                                               const float* __restrict__ W,
                                               __half2* __restrict__ hout2,
                                               int scale_out) {
    __shared__ float4 sW4[32 * 32];     // 16 KB packed W
    __shared__ float2 sMixT[32 * 66];   // 16.9 KB: [kp][n]

    for (int i = threadIdx.x; i < NH * NH; i += 256) {
        int k = i >> 6, j = i & 63;     // W row-major [k][j]
        int j2 = j >> 1, kp = k >> 1;
        int sel = ((j & 1) << 1) | (k & 1);
        ((float*)sW4)[j2 * 128 + (((kp + j2) & 31) << 2) + sel] = W[i];
    }

    int warp = threadIdx.x >> 5, lane = threadIdx.x & 31;
    int nodebase = blockIdx.x * 64;

    // gather 8 nodes per warp
    for (int m = 0; m < 8; m++) {
        int nl = warp * 8 + m;
        int node = nodebase + nl;
        float ax0 = 0.f, ay0 = 0.f, ax1 = 0.f, ay1 = 0.f;
        float mx = 0.f, my = 0.f;
        if (node < N_NODESC) {
            int s = g_rowptr[node], e = g_rowptr[node + 1];
            int i = s;
            for (; i + 4 <= e; i += 4) {
                int s0 = __ldg(&g_src[i]);
                int s1 = __ldg(&g_src[i + 1]);
                int s2 = __ldg(&g_src[i + 2]);
                int s3 = __ldg(&g_src[i + 3]);
                float2 v0 = __half22float2(__ldg(&hin2[s0 * NH2 + lane]));
                float2 v1 = __half22float2(__ldg(&hin2[s1 * NH2 + lane]));
                float2 v2 = __half22float2(__ldg(&hin2[s2 * NH2 + lane]));
                float2 v3 = __half22float2(__ldg(&hin2[s3 * NH2 + lane]));
                ax0 += v0.x; ay0 += v0.y;
                ax1 += v1.x; ay1 += v1.y;
                ax0 += v2.x; ay0 += v2.y;
                ax1 += v3.x; ay1 += v3.y;
            }
            for (; i < e; i++) {
                int s0 = __ldg(&g_src[i]);
                float2 v0 = __half22float2(__ldg(&hin2[s0 * NH2 + lane]));
                ax0 += v0.x; ay0 += v0.y;
            }
            float ax = ax0 + ax1, ay = ay0 + ay1;
            float2 h0v = *(const float2*)&h0[(long)node * NH + lane * 2];
            float dv = g_dinv[node];
            mx = fmaf(0.9f * dv, ax, 0.1f * h0v.x);
            my = fmaf(0.9f * dv, ay, 0.1f * h0v.y);
        }
        sMixT[lane * 66 + nl] = make_float2(mx, my);
    }
    __syncthreads();

    // matmul
    int j2 = lane, nq = warp;
    u64b a0[8], a1[8];
    #pragma unroll
    for (int n = 0; n < 8; n++) { a0[n] = 0ULL; a1[n] = 0ULL; }

    #pragma unroll 4
    for (int kp = 0; kp < 32; kp++) {
        F4U wv; wv.v = sW4[j2 * 32 + ((kp + j2) & 31)];
        const float2* mrow = &sMixT[kp * 66 + nq * 8];
        #pragma unroll
        for (int p = 0; p < 4; p++) {
            F4U mp; mp.v = *(const float4*)&mrow[2 * p];
            ffma2(a0[2 * p],     mp.d[0], wv.d[0]);
            ffma2(a1[2 * p],     mp.d[0], wv.d[1]);
            ffma2(a0[2 * p + 1], mp.d[1], wv.d[0]);
            ffma2(a1[2 * p + 1], mp.d[1], wv.d[1]);
        }
    }

    #pragma unroll
    for (int n = 0; n < 8; n++) {
        int node = nodebase + nq * 8 + n;
        if (node < N_NODESC) {
            float2 f0 = unpack2(a0[n]);
            float2 f1 = unpack2(a1[n]);
            float o0 = fmaxf(f0.x + f0.y, 0.f);
            float o1 = fmaxf(f1.x + f1.y, 0.f);
            float sc = scale_out ? g_dinv[node] : 1.0f;
            hout2[node * NH2 + j2] = __floats2half2_rn(o0 * sc, o1 * sc);
        }
    }
}

// ---------------- fc2: out = h @ W2^T + b2, split-K f32x2 ----------------
#define SW2S 66
#define SH2S 66
__global__ __launch_bounds__(320, 4) void k_fc2(const __half2* __restrict__ hin2,
                                                const float* __restrict__ w,
                                                const float* __restrict__ b,
                                                float* __restrict__ out) {
    __shared__ float sW[OUT_CHC * SW2S];
    __shared__ float sH[8 * SH2S];
    __shared__ float sB[OUT_CHC];
    for (int i = threadIdx.x; i < OUT_CHC * NH / 2; i += 320) {
        int j = i >> 5, kp = i & 31;
        *(float2*)&sW[j * SW2S + 2 * kp] = *(const float2*)&w[j * NH + 2 * kp];
    }
    if (threadIdx.x < OUT_CHC) sB[threadIdx.x] = b[threadIdx.x];
    __syncthreads();

    int tn = threadIdx.x / OUT_CHC;
    int j  = threadIdx.x % OUT_CHC;
    const int ngroups = N_NODESC / 8;

    for (int g = blockIdx.x; g < ngroups; g += gridDim.x) {
        int base = g * 8;
        __syncthreads();
        for (int i = threadIdx.x; i < 8 * NH2; i += 320) {
            int n = i >> 5, k2 = i & 31;
            float2 v = __half22float2(hin2[(base + n) * NH2 + k2]);
            *(float2*)&sH[n * SH2S + 2 * k2] = v;
        }
        __syncthreads();
        u64b acc = 0ULL;
        #pragma unroll 8
        for (int kp = 0; kp < NH / 2; kp++) {
            u64b a  = *(const u64b*)&sH[tn * SH2S + 2 * kp];
            u64b wv = *(const u64b*)&sW[j * SW2S + 2 * kp];
            ffma2(acc, a, wv);
        }
        float2 f = unpack2(acc);
        out[(long)(base + tn) * OUT_CHC + j] = f.x + f.y + sB[j];
    }
}

// ---------------- launch ----------------
extern "C" void kernel_launch(void* const* d_in, const int* in_sizes, int n_in,
                              void* d_out, int out_size) {
    const float* x      = (const float*)d_in[0];
    const int*   ei     = (const int*)d_in[1];
    const float* fc1_w  = (const float*)d_in[3];
    const float* fc1_b  = (const float*)d_in[4];
    const float* conv_w = (const float*)d_in[5];
    const float* fc2_w  = (const float*)d_in[6];
    const float* fc2_b  = (const float*)d_in[7];
    float*       out    = (float*)d_out;

    const int nb_nodes  = (N_NODESC + 255) / 256;
    const int nb_epairs = (N_EDGESC / 2 + 255) / 256;

    k_init<<<nb_nodes, 256>>>(ei);              // 0
    k_degree<<<nb_epairs, 256>>>(ei);           // 1
    k_scan_bsum<<<SCAN_NBLK, SCAN_CHUNK>>>();   // 2 (also dinv)
    k_fc1<<<1563, 256>>>(x, fc1_w, fc1_b);      // 3 (profiled slot)
    k_scan_top<<<1, 128>>>();
    k_scan_within<<<SCAN_NBLK, SCAN_CHUNK>>>();
    k_scatter<<<nb_epairs, 256>>>();

    float* h0; __half2* h016; __half2* hA16; __half2* hB16;
    cudaGetSymbolAddress((void**)&h0,   g_h0);
    cudaGetSymbolAddress((void**)&h016, g_h016);
    cudaGetSymbolAddress((void**)&hA16, g_hA16);
    cudaGetSymbolAddress((void**)&hB16, g_hB16);

    const int nb_layer = (N_NODESC + 63) / 64;  // 1563
    k_layer<<<nb_layer, 256>>>(h016, h0, conv_w + 0 * NH * NH, hA16, 1);
    k_layer<<<nb_layer, 256>>>(hA16, h0, conv_w + 1 * NH * NH, hB16, 1);
    k_layer<<<nb_layer, 256>>>(hB16, h0, conv_w + 2 * NH * NH, hA16, 1);
    k_layer<<<nb_layer, 256>>>(hA16, h0, conv_w + 3 * NH * NH, hB16, 0);

    k_fc2<<<592, 320>>>(hB16, fc2_w, fc2_b, out);
}